// round 16
// baseline (speedup 1.0000x reference)
#include <cuda_runtime.h>
#include <cuda_fp16.h>

// ---------------------------------------------------------------------------
// PAConv v15: v10 + occupancy-first dual-port gemm (gemm9): o-split so each
// warp owns 16 channels (32-reg accumulators), weights 8ch const + 8ch smem,
// 256 threads, launch_bounds(256,3). fp16 scratch, fp16 gather-layout y.
// Shapes: B=4, N=4096, K=32, Cin=Cout=64, m=8, P=524288, Q=16384.
// ---------------------------------------------------------------------------

#define Pn   524288
#define Qn   16384
#define NB   4096
#define EPS  1e-5f

typedef unsigned long long ull;

// ---- scratch -------------------------------------------------------------
__device__ __half g_s0[64u * 524288u];
__device__ __half g_s1[32u * 524288u];
__device__ __half g_s2[16u * 524288u];
__device__ float g_score[524288u * 8u];
__device__ float g_h[64u * 16384u];
__device__ float g_y[16384u * 512u];      // fp32 [q][m*64+o]
__device__ __half g_yh[16384u * 512u];    // fp16 [q][o*8+m]
__device__ float g_outraw[4u * 64u * 4096u];
__device__ float g_stats[512];
__device__ float g_wt[10880];
// stats offsets: bn1 0/64 | sn0 128/192 | sn1 256/288 | sn2 320/336 | bn2 352/416

__constant__ float c_W[10880];
#define OFF_L0 0
#define OFF_CV 4224
#define OFF_L1 8320
#define OFF_L2 10368

// ---- f32x2 helpers -------------------------------------------------------
__device__ __forceinline__ ull dup2(float v) {
    ull r; asm("mov.b64 %0, {%1, %1};" : "=l"(r) : "f"(v)); return r;
}
__device__ __forceinline__ void fma2(ull& d, ull a, ull b) {
    asm("fma.rn.f32x2 %0, %1, %2, %0;" : "+l"(d) : "l"(a), "l"(b));
}
__device__ __forceinline__ float2 unpk(ull v) {
    float2 r; asm("mov.b64 {%0, %1}, %2;" : "=f"(r.x), "=f"(r.y) : "l"(v)); return r;
}

__global__ void zero_stats(float* st) {
    if (threadIdx.x < 512) st[threadIdx.x] = 0.f;
}

// transpose [O][C] -> [C][O] into staging (then D2D to c_W)
__global__ void transpose_w(
    const float* __restrict__ w0, const float* __restrict__ wc,
    const float* __restrict__ wl1, const float* __restrict__ wl2,
    float* __restrict__ dst)
{
    int t = blockIdx.x * 256 + threadIdx.x;
    if (t < 4224) {
        int o = t / 66, c = t % 66;
        dst[OFF_L0 + c * 64 + o] = w0[t];
    } else if (t < 8320) {
        int i = t - 4224, o = i >> 6, c = i & 63;
        dst[OFF_CV + c * 64 + o] = wc[i];
    } else if (t < 10368) {
        int i = t - 8320, o = i >> 6, c = i & 63;
        dst[OFF_L1 + c * 32 + o] = wl1[i];
    } else if (t < 10880) {
        int i = t - 10368, o = i >> 5, c = i & 31;
        dst[OFF_L2 + c * 16 + o] = wl2[i];
    }
}

// ---------------------------------------------------------------------------
// GEMM v15 (gemm9): out[o*P + p] = sum_c W[o,c] * act(in(c,p)).
// 256 threads = 8 warps; warp w: o-group og=w%OS (OG=O/OS=16 channels),
// point-group pg=w/OS; lane owns PL=2 contiguous points.
// Block covers 32*PL*(8/OS) points. Weights per group: first OG/2 channels
// via constant LDC.128, second OG/2 via block-staged smem LDS.128.
template<int C, int O, int OS, int PL, bool ACT, typename InT, typename OutT>
__global__ __launch_bounds__(256, 3) void gemm9(
    const InT* __restrict__ in, int woff,
    const float* __restrict__ sum, const float* __restrict__ sq,
    const float* __restrict__ gam, const float* __restrict__ bet,
    OutT* __restrict__ out, int P, int PB, long BS, float inv)
{
    constexpr int OG    = O / OS;        // channels per warp (16)
    constexpr int SC    = OG / 2;        // const-served channels per group (8)
    constexpr int NPAIR = OG / 2;        // acc pairs per warp (8)
    constexpr int PG    = 8 / OS;        // point groups
    constexpr int PTS   = 32 * PL * PG;  // points per block
    static_assert(OG % 8 == 0, "OG");

    __shared__ float a_s[C], b_s[C];
    __shared__ __align__(16) float Ws[C * (O / 2)];

    const int tid  = threadIdx.x;
    const int lane = tid & 31;
    const int wid  = tid >> 5;
    const int og   = wid % OS;
    const int pg   = wid / OS;
    const int p0   = blockIdx.x * PTS;
    const int b0   = p0 / PB;
    const long ibase = (long)b0 * BS + (long)(p0 - b0 * PB);

    if (ACT) {
        if (tid < C) {
            float m   = sum[tid] * inv;
            float var = sq[tid] * inv - m * m;
            float s   = gam[tid] * rsqrtf(var + EPS);
            a_s[tid] = s;
            b_s[tid] = bet[tid] - m * s;
        }
    }
    // stage smem halves: Ws[c][ogi*SC + j] = W[c][ogi*OG + SC + j]
    for (int i = tid; i < C * (O / 2); i += 256) {
        int c   = i / (O / 2);
        int col = i - c * (O / 2);
        int ogi = col / SC;
        int j   = col - ogi * SC;
        Ws[i] = c_W[woff + c * O + ogi * OG + SC + j];
    }
    __syncthreads();

    const int pw = (pg * 32 + lane) * PL;
    const InT* ip = in + ibase + pw;

    ull acc[NPAIR][PL];
    #pragma unroll
    for (int j = 0; j < NPAIR; j++)
        #pragma unroll
        for (int t = 0; t < PL; t++) acc[j][t] = 0ull;

    constexpr int CH = (C % 8 == 0) ? 4 : 6;   // 66 -> 6, others -> 4
    static_assert(C % CH == 0, "chunk");

    for (int cc = 0; cc < C; cc += CH) {
        float v[CH][PL];
        #pragma unroll
        for (int u = 0; u < CH; u++) {
            const InT* src = ip + (long)(cc + u) * PB;
            if constexpr (sizeof(InT) == 4) {
                float2 f = *reinterpret_cast<const float2*>(src);
                v[u][0] = f.x; v[u][1] = f.y;
            } else {
                float2 f = __half22float2(*reinterpret_cast<const __half2*>(src));
                v[u][0] = f.x; v[u][1] = f.y;
            }
        }
        if (ACT) {
            #pragma unroll
            for (int u = 0; u < CH; u++) {
                float a = a_s[cc + u], b = b_s[cc + u];
                #pragma unroll
                for (int t = 0; t < PL; t++)
                    v[u][t] = fmaxf(fmaf(a, v[u][t], b), 0.f);
            }
        }
        #pragma unroll
        for (int u = 0; u < CH; u++) {
            ull in2[PL];
            #pragma unroll
            for (int t = 0; t < PL; t++) in2[t] = dup2(v[u][t]);
            // constant port: channels [og*OG, og*OG + SC)
            const ulonglong2* wpc = reinterpret_cast<const ulonglong2*>(
                c_W + woff + (cc + u) * O + og * OG);
            #pragma unroll
            for (int j2 = 0; j2 < NPAIR / 4; j2++) {
                ulonglong2 w = wpc[j2];          // LDC.128: 2 pairs
                #pragma unroll
                for (int t = 0; t < PL; t++) {
                    fma2(acc[2 * j2][t],     w.x, in2[t]);
                    fma2(acc[2 * j2 + 1][t], w.y, in2[t]);
                }
            }
            // smem port: channels [og*OG + SC, og*OG + OG)
            const ulonglong2* wps = reinterpret_cast<const ulonglong2*>(
                Ws + (cc + u) * (O / 2) + og * SC);
            #pragma unroll
            for (int j2 = 0; j2 < NPAIR / 4; j2++) {
                ulonglong2 w = wps[j2];          // broadcast LDS.128: 2 pairs
                const int jb = NPAIR / 2 + 2 * j2;
                #pragma unroll
                for (int t = 0; t < PL; t++) {
                    fma2(acc[jb][t],     w.x, in2[t]);
                    fma2(acc[jb + 1][t], w.y, in2[t]);
                }
            }
        }
    }

    const int p = p0 + pw;
    const int obase = og * OG;
    #pragma unroll
    for (int j = 0; j < NPAIR; j++) {
        float2 f0 = unpk(acc[j][0]);
        float2 f1 = unpk(acc[j][1]);
        const size_t o0 = (size_t)(obase + 2 * j) * P + p;
        const size_t o1 = (size_t)(obase + 2 * j + 1) * P + p;
        if constexpr (sizeof(OutT) == 4) {
            *reinterpret_cast<float2*>((float*)out + o0) = make_float2(f0.x, f1.x);
            *reinterpret_cast<float2*>((float*)out + o1) = make_float2(f0.y, f1.y);
        } else {
            *reinterpret_cast<__half2*>((__half*)out + o0) = __floats2half2_rn(f0.x, f1.x);
            *reinterpret_cast<__half2*>((__half*)out + o1) = __floats2half2_rn(f0.y, f1.y);
        }
    }
}

// ---------------------------------------------------------------------------
// per-channel sum/sumsq, fp32 channel-major
__global__ __launch_bounds__(256) void stats_cp(
    const float* __restrict__ s, float* __restrict__ sum, float* __restrict__ sq,
    int P, int perblock)
{
    const int c = blockIdx.y;
    const size_t base = (size_t)c * P + (size_t)blockIdx.x * perblock;
    float ls = 0.f, lq = 0.f;
    for (int i = threadIdx.x * 4; i < perblock; i += 256 * 4) {
        float4 v = *reinterpret_cast<const float4*>(s + base + i);
        ls += (v.x + v.y) + (v.z + v.w);
        lq += v.x * v.x + v.y * v.y + v.z * v.z + v.w * v.w;
    }
    #pragma unroll
    for (int o = 16; o; o >>= 1) {
        ls += __shfl_xor_sync(0xffffffffu, ls, o);
        lq += __shfl_xor_sync(0xffffffffu, lq, o);
    }
    __shared__ float ws[8], wq[8];
    if ((threadIdx.x & 31) == 0) { ws[threadIdx.x >> 5] = ls; wq[threadIdx.x >> 5] = lq; }
    __syncthreads();
    if (threadIdx.x == 0) {
        float a = 0.f, b = 0.f;
        #pragma unroll
        for (int i = 0; i < 8; i++) { a += ws[i]; b += wq[i]; }
        atomicAdd(sum + c, a);
        atomicAdd(sq + c, b);
    }
}

// per-channel sum/sumsq, fp16 channel-major
__global__ __launch_bounds__(256) void stats_h(
    const __half* __restrict__ s, float* __restrict__ sum, float* __restrict__ sq,
    int P, int perblock)
{
    const int c = blockIdx.y;
    const size_t base = (size_t)c * P + (size_t)blockIdx.x * perblock;
    float ls = 0.f, lq = 0.f;
    for (int i = threadIdx.x * 8; i < perblock; i += 256 * 8) {
        uint4 r = *reinterpret_cast<const uint4*>(s + base + i);
        float2 f0 = __half22float2(*reinterpret_cast<__half2*>(&r.x));
        float2 f1 = __half22float2(*reinterpret_cast<__half2*>(&r.y));
        float2 f2 = __half22float2(*reinterpret_cast<__half2*>(&r.z));
        float2 f3 = __half22float2(*reinterpret_cast<__half2*>(&r.w));
        ls += (f0.x + f0.y) + (f1.x + f1.y) + (f2.x + f2.y) + (f3.x + f3.y);
        lq += f0.x*f0.x + f0.y*f0.y + f1.x*f1.x + f1.y*f1.y
            + f2.x*f2.x + f2.y*f2.y + f3.x*f3.x + f3.y*f3.y;
    }
    #pragma unroll
    for (int o = 16; o; o >>= 1) {
        ls += __shfl_xor_sync(0xffffffffu, ls, o);
        lq += __shfl_xor_sync(0xffffffffu, lq, o);
    }
    __shared__ float ws[8], wq[8];
    if ((threadIdx.x & 31) == 0) { ws[threadIdx.x >> 5] = ls; wq[threadIdx.x >> 5] = lq; }
    __syncthreads();
    if (threadIdx.x == 0) {
        float a = 0.f, b = 0.f;
        #pragma unroll
        for (int i = 0; i < 8; i++) { a += ws[i]; b += wq[i]; }
        atomicAdd(sum + c, a);
        atomicAdd(sq + c, b);
    }
}

// stats over outr layout [b][o][n]
__global__ __launch_bounds__(256) void stats_bon(
    const float* __restrict__ outr, float* __restrict__ sum, float* __restrict__ sq)
{
    const int o = blockIdx.x, b = blockIdx.y;
    const float* ptr = outr + ((size_t)b * 64 + o) * NB;
    float ls = 0.f, lq = 0.f;
    for (int i = threadIdx.x * 4; i < NB; i += 256 * 4) {
        float4 v = *reinterpret_cast<const float4*>(ptr + i);
        ls += (v.x + v.y) + (v.z + v.w);
        lq += v.x * v.x + v.y * v.y + v.z * v.z + v.w * v.w;
    }
    #pragma unroll
    for (int s = 16; s; s >>= 1) {
        ls += __shfl_xor_sync(0xffffffffu, ls, s);
        lq += __shfl_xor_sync(0xffffffffu, lq, s);
    }
    __shared__ float ws[8], wq[8];
    if ((threadIdx.x & 31) == 0) { ws[threadIdx.x >> 5] = ls; wq[threadIdx.x >> 5] = lq; }
    __syncthreads();
    if (threadIdx.x == 0) {
        float a = 0.f, c2 = 0.f;
        #pragma unroll
        for (int i = 0; i < 8; i++) { a += ws[i]; c2 += wq[i]; }
        atomicAdd(sum + o, a);
        atomicAdd(sq + o, c2);
    }
}

// ---------------------------------------------------------------------------
// y GEMM: y[q][k2] = sum_c relu(a1*h[c][q]+b1)*M2[c][k2]; bn1 finalize inline.
__global__ __launch_bounds__(256) void ygemm(
    const float* __restrict__ h, const float* __restrict__ M2,
    const float* __restrict__ sum, const float* __restrict__ sq,
    const float* __restrict__ gam, const float* __restrict__ bet,
    float* __restrict__ y, float inv)
{
    extern __shared__ float sm[];
    float* As  = sm;
    float* Bs  = sm + 64 * 128;
    float* a_s = Bs + 64 * 64;
    float* b_s = a_s + 64;

    const int tid = threadIdx.x;
    const int q0  = blockIdx.x * 128;
    const int k20 = blockIdx.y * 64;

    if (tid < 64) {
        float m   = sum[tid] * inv;
        float var = sq[tid] * inv - m * m;
        float s   = gam[tid] * rsqrtf(var + EPS);
        a_s[tid] = s;
        b_s[tid] = bet[tid] - m * s;
    }
    __syncthreads();

    for (int i = tid; i < 64 * 128; i += 256) {
        int c = i >> 7, ql = i & 127;
        float v = h[c * Qn + q0 + ql];
        As[i] = fmaxf(fmaf(a_s[c], v, b_s[c]), 0.f);
    }
    for (int i = tid; i < 64 * 64; i += 256) {
        int c = i >> 6, j = i & 63;
        Bs[i] = M2[c * 512 + k20 + j];
    }
    __syncthreads();

    const int kb = (tid & 7) * 8;
    const int qb = (tid >> 3) * 4;
    ull acc[2][8];
    #pragma unroll
    for (int t = 0; t < 2; t++)
        #pragma unroll
        for (int j = 0; j < 8; j++) acc[t][j] = 0ull;

    #pragma unroll 2
    for (int c = 0; c < 64; c++) {
        ulonglong2 ap = *reinterpret_cast<const ulonglong2*>(As + c * 128 + qb);
        ull av[2] = { ap.x, ap.y };
        ull bv[8];
        #pragma unroll
        for (int j = 0; j < 8; j++) bv[j] = dup2(Bs[c * 64 + kb + j]);
        #pragma unroll
        for (int t = 0; t < 2; t++)
            #pragma unroll
            for (int j = 0; j < 8; j++)
                fma2(acc[t][j], av[t], bv[j]);
    }

    #pragma unroll
    for (int t = 0; t < 2; t++) {
        float r0[8], r1[8];
        #pragma unroll
        for (int j = 0; j < 8; j++) {
            float2 f = unpk(acc[t][j]);
            r0[j] = f.x; r1[j] = f.y;
        }
        float* d0 = y + (size_t)(q0 + qb + 2 * t) * 512 + k20 + kb;
        float* d1 = d0 + 512;
        *reinterpret_cast<float4*>(d0)     = make_float4(r0[0], r0[1], r0[2], r0[3]);
        *reinterpret_cast<float4*>(d0 + 4) = make_float4(r0[4], r0[5], r0[6], r0[7]);
        *reinterpret_cast<float4*>(d1)     = make_float4(r1[0], r1[1], r1[2], r1[3]);
        *reinterpret_cast<float4*>(d1 + 4) = make_float4(r1[4], r1[5], r1[6], r1[7]);
    }
}

// ---------------------------------------------------------------------------
// transpose y [q][m*64+o] fp32 -> yh [q][o*8+m] fp16. 4 q-rows per block.
__global__ __launch_bounds__(128) void ytrans(
    const float* __restrict__ y, __half* __restrict__ yh)
{
    __shared__ float sm4[4 * 512];
    const int tid = threadIdx.x;
    const int q0  = blockIdx.x * 4;

    for (int i = tid * 4; i < 2048; i += 128 * 4)
        *reinterpret_cast<float4*>(sm4 + i) =
            *reinterpret_cast<const float4*>(y + (size_t)q0 * 512 + i);
    __syncthreads();

    for (int i = tid; i < 1024; i += 128) {
        int q  = i >> 8;
        int pi = i & 255;
        int o  = pi >> 2;
        int j  = pi & 3;
        float a = sm4[q * 512 + (2 * j)     * 64 + o];
        float b = sm4[q * 512 + (2 * j + 1) * 64 + o];
        reinterpret_cast<__half2*>(yh)[(size_t)(q0 + q) * 256 + pi] =
            __floats2half2_rn(a, b);
    }
}

// ---------------------------------------------------------------------------
// ScoreNet layer3 (16 -> 8, fp16 in) + bias + softmax; sn2 finalize inline.
__global__ __launch_bounds__(256) void l3_softmax(
    const __half* __restrict__ s2, const float* __restrict__ w3,
    const float* __restrict__ bias3,
    const float* __restrict__ sum, const float* __restrict__ sq,
    const float* __restrict__ gam, const float* __restrict__ bet,
    float* __restrict__ score, float inv)
{
    __shared__ float W[128], B3[8], A2[16], B2[16];
    const int tid = threadIdx.x;
    if (tid < 128) W[tid] = w3[tid];
    if (tid < 8)   B3[tid] = bias3[tid];
    if (tid < 16) {
        float m   = sum[tid] * inv;
        float var = sq[tid] * inv - m * m;
        float s   = gam[tid] * rsqrtf(var + EPS);
        A2[tid] = s;
        B2[tid] = bet[tid] - m * s;
    }
    __syncthreads();

    const int p = blockIdx.x * 256 + tid;
    float v[16];
    #pragma unroll
    for (int c = 0; c < 16; c++) {
        float raw = __half2float(s2[(size_t)c * Pn + p]);
        v[c] = fmaxf(fmaf(A2[c], raw, B2[c]), 0.f);
    }
    float z[8];
    #pragma unroll
    for (int mi = 0; mi < 8; mi++) {
        float acc = B3[mi];
        #pragma unroll
        for (int c = 0; c < 16; c++) acc = fmaf(W[mi * 16 + c], v[c], acc);
        z[mi] = acc;
    }
    float mx = z[0];
    #pragma unroll
    for (int mi = 1; mi < 8; mi++) mx = fmaxf(mx, z[mi]);
    float se = 0.f;
    #pragma unroll
    for (int mi = 0; mi < 8; mi++) { z[mi] = __expf(z[mi] - mx); se += z[mi]; }
    float is = 1.f / se;
    float* dst = score + (size_t)p * 8;
    *reinterpret_cast<float4*>(dst)     = make_float4(z[0]*is, z[1]*is, z[2]*is, z[3]*is);
    *reinterpret_cast<float4*>(dst + 4) = make_float4(z[4]*is, z[5]*is, z[6]*is, z[7]*is);
}

// ---------------------------------------------------------------------------
// gather + weighted sum over fp16 y in [q][o*8+m] layout: 1 LDG.128 per k.
__global__ __launch_bounds__(64) void gather_k(
    const __half* __restrict__ yh, const float* __restrict__ score,
    const int* __restrict__ idx, float* __restrict__ outr)
{
    __shared__ int id[32];
    __shared__ __align__(16) float sc[32][8];
    const int q   = blockIdx.x;
    const int tid = threadIdx.x;          // = o
    const int b   = q >> 12;
    const int n   = q & 4095;

    if (tid < 32) id[tid] = idx[(size_t)q * 32 + tid];
    reinterpret_cast<float4*>(sc)[tid] =
        reinterpret_cast<const float4*>(score + (size_t)q * 256)[tid];
    __syncthreads();

    const int oo = tid << 3;
    float acc0 = 0.f, acc1 = 0.f;
    #pragma unroll 4
    for (int k = 0; k < 32; k++) {
        const __half* yr = yh + ((size_t)(b << 12) + id[k]) * 512 + oo;
        uint4 r = *reinterpret_cast<const uint4*>(yr);
        float2 f0 = __half22float2(*reinterpret_cast<__half2*>(&r.x));
        float2 f1 = __half22float2(*reinterpret_cast<__half2*>(&r.y));
        float2 f2 = __half22float2(*reinterpret_cast<__half2*>(&r.z));
        float2 f3 = __half22float2(*reinterpret_cast<__half2*>(&r.w));
        float4 sA = *reinterpret_cast<const float4*>(&sc[k][0]);
        float4 sB = *reinterpret_cast<const float4*>(&sc[k][4]);
        acc0 = fmaf(sA.x, f0.x, acc0);
        acc1 = fmaf(sA.y, f0.y, acc1);
        acc0 = fmaf(sA.z, f1.x, acc0);
        acc1 = fmaf(sA.w, f1.y, acc1);
        acc0 = fmaf(sB.x, f2.x, acc0);
        acc1 = fmaf(sB.y, f2.y, acc1);
        acc0 = fmaf(sB.z, f3.x, acc0);
        acc1 = fmaf(sB.w, f3.y, acc1);
    }
    outr[((size_t)(b * 64 + tid)) * NB + n] = acc0 + acc1;
}

// final bn2 + relu, finalize inline
__global__ __launch_bounds__(256) void apply_bn2(
    const float* __restrict__ outr,
    const float* __restrict__ sum, const float* __restrict__ sq,
    const float* __restrict__ gam, const float* __restrict__ bet,
    float* __restrict__ out, float inv)
{
    __shared__ float a_s[64], b_s[64];
    const int tid = threadIdx.x;
    if (tid < 64) {
        float m   = sum[tid] * inv;
        float var = sq[tid] * inv - m * m;
        float s   = gam[tid] * rsqrtf(var + EPS);
        a_s[tid] = s;
        b_s[tid] = bet[tid] - m * s;
    }
    __syncthreads();
    int i = blockIdx.x * 256 + tid;
    int o = (i >> 12) & 63;
    out[i] = fmaxf(fmaf(a_s[o], outr[i], b_s[o]), 0.f);
}

// ---------------------------------------------------------------------------
extern "C" void kernel_launch(void* const* d_in, const int* in_sizes, int n_in,
                              void* d_out, int out_size)
{
    const float* x     = (const float*)d_in[0];
    const float* xyz   = (const float*)d_in[1];
    const float* w1    = (const float*)d_in[2];
    const float* bn1g  = (const float*)d_in[3];
    const float* bn1b  = (const float*)d_in[4];
    const float* m2    = (const float*)d_in[5];
    const float* sw0   = (const float*)d_in[6];
    const float* sg0   = (const float*)d_in[7];
    const float* sb0   = (const float*)d_in[8];
    const float* sw1   = (const float*)d_in[9];
    const float* sg1   = (const float*)d_in[10];
    const float* sb1   = (const float*)d_in[11];
    const float* sw2   = (const float*)d_in[12];
    const float* sg2   = (const float*)d_in[13];
    const float* sb2   = (const float*)d_in[14];
    const float* sw3   = (const float*)d_in[15];
    const float* sbs3  = (const float*)d_in[16];
    const float* bn2g  = (const float*)d_in[17];
    const float* bn2b  = (const float*)d_in[18];
    const int*   idx   = (const int*)d_in[19];
    float* out = (float*)d_out;

    __half *s0, *s1, *s2, *yh;
    float *score, *h, *y, *outr, *st, *wt;
    cudaGetSymbolAddress((void**)&s0,    g_s0);
    cudaGetSymbolAddress((void**)&s1,    g_s1);
    cudaGetSymbolAddress((void**)&s2,    g_s2);
    cudaGetSymbolAddress((void**)&score, g_score);
    cudaGetSymbolAddress((void**)&h,     g_h);
    cudaGetSymbolAddress((void**)&y,     g_y);
    cudaGetSymbolAddress((void**)&yh,    g_yh);
    cudaGetSymbolAddress((void**)&outr,  g_outraw);
    cudaGetSymbolAddress((void**)&st,    g_stats);
    cudaGetSymbolAddress((void**)&wt,    g_wt);

    const int sm_yg = (64*128 + 64*64 + 128) * 4;   // 49664
    cudaFuncSetAttribute((const void*)ygemm, cudaFuncAttributeMaxDynamicSharedMemorySize, sm_yg);

    const float invP = 1.f / (float)Pn;
    const float invQ = 1.f / (float)Qn;

    zero_stats<<<1, 512>>>(st);

    transpose_w<<<43, 256>>>(sw0, w1, sw1, sw2, wt);
    cudaMemcpyToSymbolAsync(c_W, wt, 10880 * sizeof(float), 0,
                            cudaMemcpyDeviceToDevice);

    // dummy launch: keeps the ncu capture slot on gemm_l0.
    zero_stats<<<1, 512>>>(st);

    // ---- ScoreNet chain ----
    gemm9<66,64,4,2,false,float,__half><<<Pn/128, 256>>>(
        xyz, OFF_L0, nullptr, nullptr, nullptr, nullptr, s0, Pn, 131072, 66L*131072, 0.f);
    stats_h<<<dim3(64, 64), 256>>>(s0, st + 128, st + 192, Pn, 8192);

    gemm9<64,32,2,2,true,__half,__half><<<Pn/256, 256>>>(
        s0, OFF_L1, st + 128, st + 192, sg0, sb0, s1, Pn, Pn, 0L, invP);
    stats_h<<<dim3(64, 32), 256>>>(s1, st + 256, st + 288, Pn, 8192);

    gemm9<32,16,1,2,true,__half,__half><<<Pn/512, 256>>>(
        s1, OFF_L2, st + 256, st + 288, sg1, sb1, s2, Pn, Pn, 0L, invP);
    stats_h<<<dim3(64, 16), 256>>>(s2, st + 320, st + 336, Pn, 8192);

    l3_softmax<<<Pn/256, 256>>>(
        s2, sw3, sbs3, st + 320, st + 336, sg2, sb2, score, invP);

    // ---- main path ----
    gemm9<64,64,4,2,false,float,float><<<Qn/128, 256>>>(
        x, OFF_CV, nullptr, nullptr, nullptr, nullptr, h, Qn, 4096, 64L*4096, 0.f);
    stats_cp<<<dim3(2, 64), 256>>>(h, st + 0, st + 64, Qn, 8192);

    ygemm<<<dim3(Qn/128, 8), 256, sm_yg>>>(
        h, m2, st + 0, st + 64, bn1g, bn1b, y, invQ);
    ytrans<<<Qn/4, 128>>>(y, yh);

    // ---- gather + bn2 ----
    gather_k<<<Qn, 64>>>(yh, score, idx, outr);
    stats_bon<<<dim3(64, 4), 256>>>(outr, st + 352, st + 416);
    apply_bn2<<<4096, 256>>>(outr, st + 352, st + 416, bn2g, bn2b, out, invQ);
}

// round 17
// speedup vs baseline: 1.4294x; 1.4294x over previous
#include <cuda_runtime.h>
#include <cuda_fp16.h>

// ---------------------------------------------------------------------------
// PAConv v16: exact v10 kernels (best: 426us) + stream overlap of the main
// path (conv1/ygemm/ytrans) with the ScoreNet chain via capture-legal
// event fork/join. fp16 ScoreNet scratch, fp16 gather-layout y.
// Shapes: B=4, N=4096, K=32, Cin=Cout=64, m=8, P=524288, Q=16384.
// ---------------------------------------------------------------------------

#define Pn   524288
#define Qn   16384
#define NB   4096
#define EPS  1e-5f

typedef unsigned long long ull;

// ---- scratch -------------------------------------------------------------
__device__ __half g_s0[64u * 524288u];
__device__ __half g_s1[32u * 524288u];
__device__ __half g_s2[16u * 524288u];
__device__ float g_score[524288u * 8u];
__device__ float g_h[64u * 16384u];
__device__ float g_y[16384u * 512u];      // fp32 [q][m*64+o]
__device__ __half g_yh[16384u * 512u];    // fp16 [q][o*8+m]
__device__ float g_outraw[4u * 64u * 4096u];
__device__ float g_stats[512];
__device__ float g_wt[10880];
// stats offsets: bn1 0/64 | sn0 128/192 | sn1 256/288 | sn2 320/336 | bn2 352/416

__constant__ float c_W[10880];
#define OFF_L0 0
#define OFF_CV 4224
#define OFF_L1 8320
#define OFF_L2 10368

// ---- f32x2 helpers -------------------------------------------------------
__device__ __forceinline__ ull dup2(float v) {
    ull r; asm("mov.b64 %0, {%1, %1};" : "=l"(r) : "f"(v)); return r;
}
__device__ __forceinline__ void fma2(ull& d, ull a, ull b) {
    asm("fma.rn.f32x2 %0, %1, %2, %0;" : "+l"(d) : "l"(a), "l"(b));
}
__device__ __forceinline__ float2 unpk(ull v) {
    float2 r; asm("mov.b64 {%0, %1}, %2;" : "=f"(r.x), "=f"(r.y) : "l"(v)); return r;
}

__global__ void zero_stats(float* st) {
    if (threadIdx.x < 512) st[threadIdx.x] = 0.f;
}

// transpose [O][C] -> [C][O] into staging (then D2D to c_W)
__global__ void transpose_w(
    const float* __restrict__ w0, const float* __restrict__ wc,
    const float* __restrict__ wl1, const float* __restrict__ wl2,
    float* __restrict__ dst)
{
    int t = blockIdx.x * 256 + threadIdx.x;
    if (t < 4224) {
        int o = t / 66, c = t % 66;
        dst[OFF_L0 + c * 64 + o] = w0[t];
    } else if (t < 8320) {
        int i = t - 4224, o = i >> 6, c = i & 63;
        dst[OFF_CV + c * 64 + o] = wc[i];
    } else if (t < 10368) {
        int i = t - 8320, o = i >> 6, c = i & 63;
        dst[OFF_L1 + c * 32 + o] = wl1[i];
    } else if (t < 10880) {
        int i = t - 10368, o = i >> 5, c = i & 31;
        dst[OFF_L2 + c * 16 + o] = wl2[i];
    }
}

// ---------------------------------------------------------------------------
// GEMM (v10): out[o*P + p] = sum_c W[o,c] * act(in(c,p)); weights via LDCU.128.
// 128 threads; lane owns PL contiguous points; block covers 128*PL points.
template<int C, int O, int PL, bool ACT, typename InT, typename OutT>
__global__ __launch_bounds__(128, 4) void gemm6(
    const InT* __restrict__ in, int woff,
    const float* __restrict__ sum, const float* __restrict__ sq,
    const float* __restrict__ gam, const float* __restrict__ bet,
    OutT* __restrict__ out, int P, int PB, long BS, float inv)
{
    __shared__ float a_s[C], b_s[C];

    const int tid  = threadIdx.x;
    const int lane = tid & 31;
    const int wid  = tid >> 5;
    const int p0   = blockIdx.x * (128 * PL);
    const int b0   = p0 / PB;
    const long ibase = (long)b0 * BS + (long)(p0 - b0 * PB);

    if (ACT) {
        if (tid < C) {
            float m   = sum[tid] * inv;
            float var = sq[tid] * inv - m * m;
            float s   = gam[tid] * rsqrtf(var + EPS);
            a_s[tid] = s;
            b_s[tid] = bet[tid] - m * s;
        }
        __syncthreads();
    }

    const int pw = (wid * 32 + lane) * PL;
    const InT* ip = in + ibase + pw;

    ull acc[O / 2][PL];
    #pragma unroll
    for (int j = 0; j < O / 2; j++)
        #pragma unroll
        for (int t = 0; t < PL; t++) acc[j][t] = 0ull;

    constexpr int CH = (PL >= 4) ? 4 : ((C % 8 == 0) ? 8 : 6);
    static_assert(C % CH == 0, "chunk");

    for (int cc = 0; cc < C; cc += CH) {
        float v[CH][PL];
        #pragma unroll
        for (int u = 0; u < CH; u++) {
            const InT* src = ip + (long)(cc + u) * PB;
            if constexpr (sizeof(InT) == 4) {
                if (PL == 1) {
                    v[u][0] = ((const float*)src)[0];
                } else if (PL == 2) {
                    float2 f = *reinterpret_cast<const float2*>(src);
                    v[u][0] = f.x; v[u][1] = f.y;
                } else {
                    float4 f = *reinterpret_cast<const float4*>(src);
                    v[u][0] = f.x; v[u][1] = f.y; v[u][2] = f.z; v[u][3] = f.w;
                }
            } else {
                if (PL == 1) {
                    v[u][0] = __half2float(*(const __half*)src);
                } else if (PL == 2) {
                    float2 f = __half22float2(*reinterpret_cast<const __half2*>(src));
                    v[u][0] = f.x; v[u][1] = f.y;
                } else {
                    uint2 r = *reinterpret_cast<const uint2*>(src);
                    float2 fa = __half22float2(*reinterpret_cast<__half2*>(&r.x));
                    float2 fb = __half22float2(*reinterpret_cast<__half2*>(&r.y));
                    v[u][0] = fa.x; v[u][1] = fa.y; v[u][2] = fb.x; v[u][3] = fb.y;
                }
            }
        }
        if (ACT) {
            #pragma unroll
            for (int u = 0; u < CH; u++) {
                float a = a_s[cc + u], b = b_s[cc + u];
                #pragma unroll
                for (int t = 0; t < PL; t++)
                    v[u][t] = fmaxf(fmaf(a, v[u][t], b), 0.f);
            }
        }
        #pragma unroll
        for (int u = 0; u < CH; u++) {
            ull in2[PL];
            #pragma unroll
            for (int t = 0; t < PL; t++) in2[t] = dup2(v[u][t]);
            const ulonglong2* wp =
                reinterpret_cast<const ulonglong2*>(c_W + woff + (cc + u) * O);
            #pragma unroll
            for (int j2 = 0; j2 < O / 4; j2++) {
                ulonglong2 w = wp[j2];       // LDCU.128: 2 channel-pairs
                #pragma unroll
                for (int t = 0; t < PL; t++) {
                    fma2(acc[2 * j2][t],     w.x, in2[t]);
                    fma2(acc[2 * j2 + 1][t], w.y, in2[t]);
                }
            }
        }
    }

    const int p = p0 + pw;
    #pragma unroll
    for (int j = 0; j < O / 2; j++) {
        if constexpr (sizeof(OutT) == 4) {
            float* o0 = (float*)out + (size_t)(2 * j) * P + p;
            float* o1 = (float*)out + (size_t)(2 * j + 1) * P + p;
            if (PL == 1) {
                float2 f = unpk(acc[j][0]);
                o0[0] = f.x; o1[0] = f.y;
            } else if (PL == 2) {
                float2 f0 = unpk(acc[j][0]), f1 = unpk(acc[j][1]);
                *reinterpret_cast<float2*>(o0) = make_float2(f0.x, f1.x);
                *reinterpret_cast<float2*>(o1) = make_float2(f0.y, f1.y);
            } else {
                float2 f0 = unpk(acc[j][0]), f1 = unpk(acc[j][1]);
                float2 f2 = unpk(acc[j][2]), f3 = unpk(acc[j][3]);
                *reinterpret_cast<float4*>(o0) = make_float4(f0.x, f1.x, f2.x, f3.x);
                *reinterpret_cast<float4*>(o1) = make_float4(f0.y, f1.y, f2.y, f3.y);
            }
        } else {
            __half* o0 = (__half*)out + (size_t)(2 * j) * P + p;
            __half* o1 = (__half*)out + (size_t)(2 * j + 1) * P + p;
            if (PL == 1) {
                float2 f = unpk(acc[j][0]);
                o0[0] = __float2half_rn(f.x);
                o1[0] = __float2half_rn(f.y);
            } else if (PL == 2) {
                float2 f0 = unpk(acc[j][0]), f1 = unpk(acc[j][1]);
                *reinterpret_cast<__half2*>(o0) = __floats2half2_rn(f0.x, f1.x);
                *reinterpret_cast<__half2*>(o1) = __floats2half2_rn(f0.y, f1.y);
            } else {
                float2 f0 = unpk(acc[j][0]), f1 = unpk(acc[j][1]);
                float2 f2 = unpk(acc[j][2]), f3 = unpk(acc[j][3]);
                __half2 h0a = __floats2half2_rn(f0.x, f1.x);
                __half2 h0b = __floats2half2_rn(f2.x, f3.x);
                __half2 h1a = __floats2half2_rn(f0.y, f1.y);
                __half2 h1b = __floats2half2_rn(f2.y, f3.y);
                uint2 u0, u1;
                u0.x = *reinterpret_cast<unsigned*>(&h0a);
                u0.y = *reinterpret_cast<unsigned*>(&h0b);
                u1.x = *reinterpret_cast<unsigned*>(&h1a);
                u1.y = *reinterpret_cast<unsigned*>(&h1b);
                *reinterpret_cast<uint2*>(o0) = u0;
                *reinterpret_cast<uint2*>(o1) = u1;
            }
        }
    }
}

// ---------------------------------------------------------------------------
// per-channel sum/sumsq, fp32 channel-major
__global__ __launch_bounds__(256) void stats_cp(
    const float* __restrict__ s, float* __restrict__ sum, float* __restrict__ sq,
    int P, int perblock)
{
    const int c = blockIdx.y;
    const size_t base = (size_t)c * P + (size_t)blockIdx.x * perblock;
    float ls = 0.f, lq = 0.f;
    for (int i = threadIdx.x * 4; i < perblock; i += 256 * 4) {
        float4 v = *reinterpret_cast<const float4*>(s + base + i);
        ls += (v.x + v.y) + (v.z + v.w);
        lq += v.x * v.x + v.y * v.y + v.z * v.z + v.w * v.w;
    }
    #pragma unroll
    for (int o = 16; o; o >>= 1) {
        ls += __shfl_xor_sync(0xffffffffu, ls, o);
        lq += __shfl_xor_sync(0xffffffffu, lq, o);
    }
    __shared__ float ws[8], wq[8];
    if ((threadIdx.x & 31) == 0) { ws[threadIdx.x >> 5] = ls; wq[threadIdx.x >> 5] = lq; }
    __syncthreads();
    if (threadIdx.x == 0) {
        float a = 0.f, b = 0.f;
        #pragma unroll
        for (int i = 0; i < 8; i++) { a += ws[i]; b += wq[i]; }
        atomicAdd(sum + c, a);
        atomicAdd(sq + c, b);
    }
}

// per-channel sum/sumsq, fp16 channel-major
__global__ __launch_bounds__(256) void stats_h(
    const __half* __restrict__ s, float* __restrict__ sum, float* __restrict__ sq,
    int P, int perblock)
{
    const int c = blockIdx.y;
    const size_t base = (size_t)c * P + (size_t)blockIdx.x * perblock;
    float ls = 0.f, lq = 0.f;
    for (int i = threadIdx.x * 8; i < perblock; i += 256 * 8) {
        uint4 r = *reinterpret_cast<const uint4*>(s + base + i);
        float2 f0 = __half22float2(*reinterpret_cast<__half2*>(&r.x));
        float2 f1 = __half22float2(*reinterpret_cast<__half2*>(&r.y));
        float2 f2 = __half22float2(*reinterpret_cast<__half2*>(&r.z));
        float2 f3 = __half22float2(*reinterpret_cast<__half2*>(&r.w));
        ls += (f0.x + f0.y) + (f1.x + f1.y) + (f2.x + f2.y) + (f3.x + f3.y);
        lq += f0.x*f0.x + f0.y*f0.y + f1.x*f1.x + f1.y*f1.y
            + f2.x*f2.x + f2.y*f2.y + f3.x*f3.x + f3.y*f3.y;
    }
    #pragma unroll
    for (int o = 16; o; o >>= 1) {
        ls += __shfl_xor_sync(0xffffffffu, ls, o);
        lq += __shfl_xor_sync(0xffffffffu, lq, o);
    }
    __shared__ float ws[8], wq[8];
    if ((threadIdx.x & 31) == 0) { ws[threadIdx.x >> 5] = ls; wq[threadIdx.x >> 5] = lq; }
    __syncthreads();
    if (threadIdx.x == 0) {
        float a = 0.f, b = 0.f;
        #pragma unroll
        for (int i = 0; i < 8; i++) { a += ws[i]; b += wq[i]; }
        atomicAdd(sum + c, a);
        atomicAdd(sq + c, b);
    }
}

// stats over outr layout [b][o][n]
__global__ __launch_bounds__(256) void stats_bon(
    const float* __restrict__ outr, float* __restrict__ sum, float* __restrict__ sq)
{
    const int o = blockIdx.x, b = blockIdx.y;
    const float* ptr = outr + ((size_t)b * 64 + o) * NB;
    float ls = 0.f, lq = 0.f;
    for (int i = threadIdx.x * 4; i < NB; i += 256 * 4) {
        float4 v = *reinterpret_cast<const float4*>(ptr + i);
        ls += (v.x + v.y) + (v.z + v.w);
        lq += v.x * v.x + v.y * v.y + v.z * v.z + v.w * v.w;
    }
    #pragma unroll
    for (int s = 16; s; s >>= 1) {
        ls += __shfl_xor_sync(0xffffffffu, ls, s);
        lq += __shfl_xor_sync(0xffffffffu, lq, s);
    }
    __shared__ float ws[8], wq[8];
    if ((threadIdx.x & 31) == 0) { ws[threadIdx.x >> 5] = ls; wq[threadIdx.x >> 5] = lq; }
    __syncthreads();
    if (threadIdx.x == 0) {
        float a = 0.f, c2 = 0.f;
        #pragma unroll
        for (int i = 0; i < 8; i++) { a += ws[i]; c2 += wq[i]; }
        atomicAdd(sum + o, a);
        atomicAdd(sq + o, c2);
    }
}

// ---------------------------------------------------------------------------
// y GEMM: y[q][k2] = sum_c relu(a1*h[c][q]+b1)*M2[c][k2]; bn1 finalize inline.
__global__ __launch_bounds__(256) void ygemm(
    const float* __restrict__ h, const float* __restrict__ M2,
    const float* __restrict__ sum, const float* __restrict__ sq,
    const float* __restrict__ gam, const float* __restrict__ bet,
    float* __restrict__ y, float inv)
{
    extern __shared__ float sm[];
    float* As  = sm;
    float* Bs  = sm + 64 * 128;
    float* a_s = Bs + 64 * 64;
    float* b_s = a_s + 64;

    const int tid = threadIdx.x;
    const int q0  = blockIdx.x * 128;
    const int k20 = blockIdx.y * 64;

    if (tid < 64) {
        float m   = sum[tid] * inv;
        float var = sq[tid] * inv - m * m;
        float s   = gam[tid] * rsqrtf(var + EPS);
        a_s[tid] = s;
        b_s[tid] = bet[tid] - m * s;
    }
    __syncthreads();

    for (int i = tid; i < 64 * 128; i += 256) {
        int c = i >> 7, ql = i & 127;
        float v = h[c * Qn + q0 + ql];
        As[i] = fmaxf(fmaf(a_s[c], v, b_s[c]), 0.f);
    }
    for (int i = tid; i < 64 * 64; i += 256) {
        int c = i >> 6, j = i & 63;
        Bs[i] = M2[c * 512 + k20 + j];
    }
    __syncthreads();

    const int kb = (tid & 7) * 8;
    const int qb = (tid >> 3) * 4;
    ull acc[2][8];
    #pragma unroll
    for (int t = 0; t < 2; t++)
        #pragma unroll
        for (int j = 0; j < 8; j++) acc[t][j] = 0ull;

    #pragma unroll 2
    for (int c = 0; c < 64; c++) {
        ulonglong2 ap = *reinterpret_cast<const ulonglong2*>(As + c * 128 + qb);
        ull av[2] = { ap.x, ap.y };
        ull bv[8];
        #pragma unroll
        for (int j = 0; j < 8; j++) bv[j] = dup2(Bs[c * 64 + kb + j]);
        #pragma unroll
        for (int t = 0; t < 2; t++)
            #pragma unroll
            for (int j = 0; j < 8; j++)
                fma2(acc[t][j], av[t], bv[j]);
    }

    #pragma unroll
    for (int t = 0; t < 2; t++) {
        float r0[8], r1[8];
        #pragma unroll
        for (int j = 0; j < 8; j++) {
            float2 f = unpk(acc[t][j]);
            r0[j] = f.x; r1[j] = f.y;
        }
        float* d0 = y + (size_t)(q0 + qb + 2 * t) * 512 + k20 + kb;
        float* d1 = d0 + 512;
        *reinterpret_cast<float4*>(d0)     = make_float4(r0[0], r0[1], r0[2], r0[3]);
        *reinterpret_cast<float4*>(d0 + 4) = make_float4(r0[4], r0[5], r0[6], r0[7]);
        *reinterpret_cast<float4*>(d1)     = make_float4(r1[0], r1[1], r1[2], r1[3]);
        *reinterpret_cast<float4*>(d1 + 4) = make_float4(r1[4], r1[5], r1[6], r1[7]);
    }
}

// ---------------------------------------------------------------------------
// transpose y [q][m*64+o] fp32 -> yh [q][o*8+m] fp16. 4 q-rows per block.
__global__ __launch_bounds__(128) void ytrans(
    const float* __restrict__ y, __half* __restrict__ yh)
{
    __shared__ float sm4[4 * 512];
    const int tid = threadIdx.x;
    const int q0  = blockIdx.x * 4;

    for (int i = tid * 4; i < 2048; i += 128 * 4)
        *reinterpret_cast<float4*>(sm4 + i) =
            *reinterpret_cast<const float4*>(y + (size_t)q0 * 512 + i);
    __syncthreads();

    for (int i = tid; i < 1024; i += 128) {
        int q  = i >> 8;
        int pi = i & 255;
        int o  = pi >> 2;
        int j  = pi & 3;
        float a = sm4[q * 512 + (2 * j)     * 64 + o];
        float b = sm4[q * 512 + (2 * j + 1) * 64 + o];
        reinterpret_cast<__half2*>(yh)[(size_t)(q0 + q) * 256 + pi] =
            __floats2half2_rn(a, b);
    }
}

// ---------------------------------------------------------------------------
// ScoreNet layer3 (16 -> 8, fp16 in) + bias + softmax; sn2 finalize inline.
__global__ __launch_bounds__(256) void l3_softmax(
    const __half* __restrict__ s2, const float* __restrict__ w3,
    const float* __restrict__ bias3,
    const float* __restrict__ sum, const float* __restrict__ sq,
    const float* __restrict__ gam, const float* __restrict__ bet,
    float* __restrict__ score, float inv)
{
    __shared__ float W[128], B3[8], A2[16], B2[16];
    const int tid = threadIdx.x;
    if (tid < 128) W[tid] = w3[tid];
    if (tid < 8)   B3[tid] = bias3[tid];
    if (tid < 16) {
        float m   = sum[tid] * inv;
        float var = sq[tid] * inv - m * m;
        float s   = gam[tid] * rsqrtf(var + EPS);
        A2[tid] = s;
        B2[tid] = bet[tid] - m * s;
    }
    __syncthreads();

    const int p = blockIdx.x * 256 + tid;
    float v[16];
    #pragma unroll
    for (int c = 0; c < 16; c++) {
        float raw = __half2float(s2[(size_t)c * Pn + p]);
        v[c] = fmaxf(fmaf(A2[c], raw, B2[c]), 0.f);
    }
    float z[8];
    #pragma unroll
    for (int mi = 0; mi < 8; mi++) {
        float acc = B3[mi];
        #pragma unroll
        for (int c = 0; c < 16; c++) acc = fmaf(W[mi * 16 + c], v[c], acc);
        z[mi] = acc;
    }
    float mx = z[0];
    #pragma unroll
    for (int mi = 1; mi < 8; mi++) mx = fmaxf(mx, z[mi]);
    float se = 0.f;
    #pragma unroll
    for (int mi = 0; mi < 8; mi++) { z[mi] = __expf(z[mi] - mx); se += z[mi]; }
    float is = 1.f / se;
    float* dst = score + (size_t)p * 8;
    *reinterpret_cast<float4*>(dst)     = make_float4(z[0]*is, z[1]*is, z[2]*is, z[3]*is);
    *reinterpret_cast<float4*>(dst + 4) = make_float4(z[4]*is, z[5]*is, z[6]*is, z[7]*is);
}

// ---------------------------------------------------------------------------
// gather + weighted sum over fp16 y in [q][o*8+m] layout: 1 LDG.128 per k.
__global__ __launch_bounds__(64) void gather_k(
    const __half* __restrict__ yh, const float* __restrict__ score,
    const int* __restrict__ idx, float* __restrict__ outr)
{
    __shared__ int id[32];
    __shared__ __align__(16) float sc[32][8];
    const int q   = blockIdx.x;
    const int tid = threadIdx.x;          // = o
    const int b   = q >> 12;
    const int n   = q & 4095;

    if (tid < 32) id[tid] = idx[(size_t)q * 32 + tid];
    reinterpret_cast<float4*>(sc)[tid] =
        reinterpret_cast<const float4*>(score + (size_t)q * 256)[tid];
    __syncthreads();

    const int oo = tid << 3;
    float acc0 = 0.f, acc1 = 0.f;
    #pragma unroll 4
    for (int k = 0; k < 32; k++) {
        const __half* yr = yh + ((size_t)(b << 12) + id[k]) * 512 + oo;
        uint4 r = *reinterpret_cast<const uint4*>(yr);
        float2 f0 = __half22float2(*reinterpret_cast<__half2*>(&r.x));
        float2 f1 = __half22float2(*reinterpret_cast<__half2*>(&r.y));
        float2 f2 = __half22float2(*reinterpret_cast<__half2*>(&r.z));
        float2 f3 = __half22float2(*reinterpret_cast<__half2*>(&r.w));
        float4 sA = *reinterpret_cast<const float4*>(&sc[k][0]);
        float4 sB = *reinterpret_cast<const float4*>(&sc[k][4]);
        acc0 = fmaf(sA.x, f0.x, acc0);
        acc1 = fmaf(sA.y, f0.y, acc1);
        acc0 = fmaf(sA.z, f1.x, acc0);
        acc1 = fmaf(sA.w, f1.y, acc1);
        acc0 = fmaf(sB.x, f2.x, acc0);
        acc1 = fmaf(sB.y, f2.y, acc1);
        acc0 = fmaf(sB.z, f3.x, acc0);
        acc1 = fmaf(sB.w, f3.y, acc1);
    }
    outr[((size_t)(b * 64 + tid)) * NB + n] = acc0 + acc1;
}

// final bn2 + relu, finalize inline
__global__ __launch_bounds__(256) void apply_bn2(
    const float* __restrict__ outr,
    const float* __restrict__ sum, const float* __restrict__ sq,
    const float* __restrict__ gam, const float* __restrict__ bet,
    float* __restrict__ out, float inv)
{
    __shared__ float a_s[64], b_s[64];
    const int tid = threadIdx.x;
    if (tid < 64) {
        float m   = sum[tid] * inv;
        float var = sq[tid] * inv - m * m;
        float s   = gam[tid] * rsqrtf(var + EPS);
        a_s[tid] = s;
        b_s[tid] = bet[tid] - m * s;
    }
    __syncthreads();
    int i = blockIdx.x * 256 + tid;
    int o = (i >> 12) & 63;
    out[i] = fmaxf(fmaf(a_s[o], outr[i], b_s[o]), 0.f);
}

// ---------------------------------------------------------------------------
extern "C" void kernel_launch(void* const* d_in, const int* in_sizes, int n_in,
                              void* d_out, int out_size)
{
    const float* x     = (const float*)d_in[0];
    const float* xyz   = (const float*)d_in[1];
    const float* w1    = (const float*)d_in[2];
    const float* bn1g  = (const float*)d_in[3];
    const float* bn1b  = (const float*)d_in[4];
    const float* m2    = (const float*)d_in[5];
    const float* sw0   = (const float*)d_in[6];
    const float* sg0   = (const float*)d_in[7];
    const float* sb0   = (const float*)d_in[8];
    const float* sw1   = (const float*)d_in[9];
    const float* sg1   = (const float*)d_in[10];
    const float* sb1   = (const float*)d_in[11];
    const float* sw2   = (const float*)d_in[12];
    const float* sg2   = (const float*)d_in[13];
    const float* sb2   = (const float*)d_in[14];
    const float* sw3   = (const float*)d_in[15];
    const float* sbs3  = (const float*)d_in[16];
    const float* bn2g  = (const float*)d_in[17];
    const float* bn2b  = (const float*)d_in[18];
    const int*   idx   = (const int*)d_in[19];
    float* out = (float*)d_out;

    __half *s0, *s1, *s2, *yh;
    float *score, *h, *y, *outr, *st, *wt;
    cudaGetSymbolAddress((void**)&s0,    g_s0);
    cudaGetSymbolAddress((void**)&s1,    g_s1);
    cudaGetSymbolAddress((void**)&s2,    g_s2);
    cudaGetSymbolAddress((void**)&score, g_score);
    cudaGetSymbolAddress((void**)&h,     g_h);
    cudaGetSymbolAddress((void**)&y,     g_y);
    cudaGetSymbolAddress((void**)&yh,    g_yh);
    cudaGetSymbolAddress((void**)&outr,  g_outraw);
    cudaGetSymbolAddress((void**)&st,    g_stats);
    cudaGetSymbolAddress((void**)&wt,    g_wt);

    // one-time side stream + events for capture fork/join (not allocations)
    static cudaStream_t s2s = nullptr;
    static cudaEvent_t evFork = nullptr, evJoin = nullptr;
    if (s2s == nullptr) {
        cudaStreamCreateWithFlags(&s2s, cudaStreamNonBlocking);
        cudaEventCreateWithFlags(&evFork, cudaEventDisableTiming);
        cudaEventCreateWithFlags(&evJoin, cudaEventDisableTiming);
    }

    const int sm_yg = (64*128 + 64*64 + 128) * 4;   // 49664
    cudaFuncSetAttribute((const void*)ygemm, cudaFuncAttributeMaxDynamicSharedMemorySize, sm_yg);

    const float invP = 1.f / (float)Pn;
    const float invQ = 1.f / (float)Qn;

    zero_stats<<<1, 512>>>(st);

    transpose_w<<<43, 256>>>(sw0, w1, sw1, sw2, wt);
    cudaMemcpyToSymbolAsync(c_W, wt, 10880 * sizeof(float), 0,
                            cudaMemcpyDeviceToDevice);

    // ---- fork: main path on side stream, ScoreNet chain on main stream ----
    cudaEventRecord(evFork, 0);
    cudaStreamWaitEvent(s2s, evFork, 0);

    // main path (side stream)
    gemm6<64,64,1,false,float,float><<<Qn/128, 128, 0, s2s>>>(
        x, OFF_CV, nullptr, nullptr, nullptr, nullptr, h, Qn, 4096, 64L*4096, 0.f);
    stats_cp<<<dim3(2, 64), 256, 0, s2s>>>(h, st + 0, st + 64, Qn, 8192);
    ygemm<<<dim3(Qn/128, 8), 256, sm_yg, s2s>>>(
        h, m2, st + 0, st + 64, bn1g, bn1b, y, invQ);
    ytrans<<<Qn/4, 128, 0, s2s>>>(y, yh);
    cudaEventRecord(evJoin, s2s);

    // ScoreNet chain (main stream)
    gemm6<66,64,1,false,float,__half><<<Pn/128, 128>>>(
        xyz, OFF_L0, nullptr, nullptr, nullptr, nullptr, s0, Pn, 131072, 66L*131072, 0.f);
    stats_h<<<dim3(64, 64), 256>>>(s0, st + 128, st + 192, Pn, 8192);

    gemm6<64,32,2,true,__half,__half><<<Pn/256, 128>>>(
        s0, OFF_L1, st + 128, st + 192, sg0, sb0, s1, Pn, Pn, 0L, invP);
    stats_h<<<dim3(64, 32), 256>>>(s1, st + 256, st + 288, Pn, 8192);

    gemm6<32,16,4,true,__half,__half><<<Pn/512, 128>>>(
        s1, OFF_L2, st + 256, st + 288, sg1, sb1, s2, Pn, Pn, 0L, invP);
    stats_h<<<dim3(64, 16), 256>>>(s2, st + 320, st + 336, Pn, 8192);

    l3_softmax<<<Pn/256, 256>>>(
        s2, sw3, sbs3, st + 320, st + 336, sg2, sb2, score, invP);

    // ---- join: gather needs both yh (side) and score (main) ----
    cudaStreamWaitEvent(0, evJoin, 0);

    gather_k<<<Qn, 64>>>(yh, score, idx, outr);
    stats_bon<<<dim3(64, 4), 256>>>(outr, st + 352, st + 416);
    apply_bn2<<<4096, 256>>>(outr, st + 352, st + 416, bn2g, bn2b, out, invQ);
}